// round 3
// baseline (speedup 1.0000x reference)
#include <cuda_runtime.h>
#include <cuda_fp16.h>

#define M_DIM 2048
#define N_DIM 8192
#define N_ITERS 1000
#define TAU 1e-4f
#define SIGMA 1e-4f
#define NBLK 128
#define NTHR 512
#define NWARP (NTHR / 32)

// Persistent state (allocation-free scratch: __device__ globals)
__device__ float g_x[N_DIM];
__device__ float g_xbar[N_DIM];
__device__ float g_y[M_DIM];
__device__ float g_lam[M_DIM];
__device__ unsigned int g_count;
__device__ unsigned int g_gen;
// fp16 copy of A, row-major, stored as half2 (32 MB)
__device__ __half2 g_Ah[(size_t)M_DIM * N_DIM / 2];

// ---------------------------------------------------------------------------
// Graph node 1: deterministic state reset on every replay
// ---------------------------------------------------------------------------
__global__ void init_kernel() {
    int i = blockIdx.x * blockDim.x + threadIdx.x;
    if (i < N_DIM) { g_x[i] = 0.f; g_xbar[i] = 0.f; }
    if (i < M_DIM) { g_y[i] = 0.f; }
    if (i == 0)    { g_count = 0u; g_gen = 0u; }
}

// ---------------------------------------------------------------------------
// Graph node 2: convert A (fp32) -> g_Ah (fp16), row-major
// ---------------------------------------------------------------------------
__global__ void __launch_bounds__(256) convert_kernel(const float* __restrict__ A) {
    size_t i = (size_t)blockIdx.x * 256 + threadIdx.x;   // over float4s
    const float4* A4 = reinterpret_cast<const float4*>(A);
    float4 v = A4[i];
    g_Ah[2 * i]     = __floats2half2_rn(v.x, v.y);
    g_Ah[2 * i + 1] = __floats2half2_rn(v.z, v.w);
}

// ---------------------------------------------------------------------------
// Software grid barrier (sense via monotonically increasing generation).
// 128 blocks, 1 per SM, guaranteed co-resident.
// ---------------------------------------------------------------------------
__device__ __forceinline__ void grid_sync() {
    __syncthreads();
    if (threadIdx.x == 0) {
        volatile unsigned int* vgen = &g_gen;
        unsigned int gen = *vgen;
        __threadfence();                       // release our writes GPU-wide
        unsigned int t = atomicAdd(&g_count, 1u);
        if (t == NBLK - 1) {
            g_count = 0u;
            __threadfence();
            atomicAdd(&g_gen, 1u);             // release all
        } else {
            while (*vgen == gen) { }           // spin (L2 poll)
        }
        __threadfence();                       // acquire (flushes L1D)
    }
    __syncthreads();
}

// ---------------------------------------------------------------------------
// Graph node 3: the entire PDHG solve in one persistent kernel.
//   Phase Y: warp per row (128 blk x 16 warps = 2048 rows), fp16 A,
//            xbar staged in smem, per-load zero-skip on xbar.
//   Phase X: block owns 64 columns; 16 row-groups; half2 loads;
//            warp-uniform row skip where y_i == 0.
// ---------------------------------------------------------------------------
__global__ void __launch_bounds__(NTHR, 1)
pdhg_kernel(const float* __restrict__ A, const float* __restrict__ b,
            const float* __restrict__ c, float* __restrict__ out) {
    __shared__ float s_vec[N_DIM];       // 32 KB: xbar stage
    __shared__ float s_y[M_DIM];         // 8 KB: y / lam stage
    __shared__ float s_red[16][64];      // 4 KB: column partial sums

    const int tid  = threadIdx.x;
    const int warp = tid >> 5;
    const int lane = tid & 31;
    const int row  = blockIdx.x * NWARP + warp;   // phase-Y row (0..2047)

    float4* s4 = reinterpret_cast<float4*>(s_vec);
    float2 (*s_red2)[32] = reinterpret_cast<float2(*)[32]>(s_red);

    for (int it = 0; it < N_ITERS; it++) {
        // ---- Phase Y: y = min(0, y + SIGMA*(A @ xbar) - SIGMA*b) ----
        {
            const float4* x4 = reinterpret_cast<const float4*>(g_xbar);
            #pragma unroll
            for (int k = 0; k < (N_DIM / 4) / NTHR; k++)
                s4[tid + k * NTHR] = x4[tid + k * NTHR];
        }
        __syncthreads();

        {
            const uint4* Arow = reinterpret_cast<const uint4*>(
                g_Ah + (size_t)row * (N_DIM / 2));
            float acc = 0.f;
            #pragma unroll 4
            for (int k = lane; k < N_DIM / 8; k += 32) {
                float4 xb0 = s4[2 * k];
                float4 xb1 = s4[2 * k + 1];
                unsigned nz = __float_as_uint(xb0.x) | __float_as_uint(xb0.y) |
                              __float_as_uint(xb0.z) | __float_as_uint(xb0.w) |
                              __float_as_uint(xb1.x) | __float_as_uint(xb1.y) |
                              __float_as_uint(xb1.z) | __float_as_uint(xb1.w);
                if (nz) {
                    uint4 a = Arow[k];
                    float2 f0 = __half22float2(*reinterpret_cast<__half2*>(&a.x));
                    float2 f1 = __half22float2(*reinterpret_cast<__half2*>(&a.y));
                    float2 f2 = __half22float2(*reinterpret_cast<__half2*>(&a.z));
                    float2 f3 = __half22float2(*reinterpret_cast<__half2*>(&a.w));
                    acc += f0.x * xb0.x + f0.y * xb0.y;
                    acc += f1.x * xb0.z + f1.y * xb0.w;
                    acc += f2.x * xb1.x + f2.y * xb1.y;
                    acc += f3.x * xb1.z + f3.y * xb1.w;
                }
            }
            #pragma unroll
            for (int o = 16; o > 0; o >>= 1)
                acc += __shfl_down_sync(0xffffffffu, acc, o);
            if (lane == 0)
                g_y[row] = fminf(0.f, g_y[row] + SIGMA * acc - SIGMA * b[row]);
        }
        grid_sync();

        // ---- Phase X: x = relu(x - TAU*(A^T @ y) - TAU*c); xbar = 2x - x_old ----
        #pragma unroll
        for (int k = 0; k < M_DIM / NTHR; k++)
            s_y[tid + k * NTHR] = g_y[tid + k * NTHR];
        __syncthreads();

        {
            const int j2 = blockIdx.x * 32 + lane;   // half2 column index
            float2 acc = make_float2(0.f, 0.f);
            #pragma unroll 8
            for (int i = warp; i < M_DIM; i += NWARP) {
                float yv = s_y[i];                    // warp-uniform broadcast
                if (yv != 0.f) {
                    __half2 a = g_Ah[(size_t)i * (N_DIM / 2) + j2];
                    float2 f = __half22float2(a);
                    acc.x += f.x * yv;
                    acc.y += f.y * yv;
                }
            }
            s_red2[warp][lane] = acc;
        }
        __syncthreads();

        if (warp == 0) {
            float2 dot = make_float2(0.f, 0.f);
            #pragma unroll
            for (int r = 0; r < NWARP; r++) {
                float2 p = s_red2[r][lane];
                dot.x += p.x; dot.y += p.y;
            }
            int j = blockIdx.x * 64 + 2 * lane;
            float xo0 = g_x[j], xo1 = g_x[j + 1];
            float xn0 = fmaxf(0.f, xo0 - TAU * dot.x - TAU * c[j]);
            float xn1 = fmaxf(0.f, xo1 - TAU * dot.y - TAU * c[j + 1]);
            g_x[j]        = xn0;
            g_x[j + 1]    = xn1;
            g_xbar[j]     = 2.f * xn0 - xo0;
            g_xbar[j + 1] = 2.f * xn1 - xo1;
        }
        grid_sync();
    }

    // ---- Finalize: out = [x, lam, nu] ----
    for (int i = blockIdx.x * NTHR + tid; i < N_DIM; i += NBLK * NTHR)
        out[i] = g_x[i];
    for (int i = blockIdx.x * NTHR + tid; i < M_DIM; i += NBLK * NTHR) {
        float l = fmaxf(0.f, -g_y[i]);
        g_lam[i] = l;
        out[N_DIM + i] = l;
    }
    grid_sync();

    // nu = relu(c - A^T @ lam), using the ORIGINAL fp32 A for accuracy
    #pragma unroll
    for (int k = 0; k < M_DIM / NTHR; k++)
        s_y[tid + k * NTHR] = g_lam[tid + k * NTHR];
    __syncthreads();

    {
        const int j0 = blockIdx.x * 64 + lane;
        float acc0 = 0.f, acc1 = 0.f;
        #pragma unroll 4
        for (int i = warp; i < M_DIM; i += NWARP) {
            float lv = s_y[i];
            if (lv != 0.f) {
                acc0 += A[(size_t)i * N_DIM + j0]      * lv;
                acc1 += A[(size_t)i * N_DIM + j0 + 32] * lv;
            }
        }
        s_red[warp][lane]      = acc0;
        s_red[warp][lane + 32] = acc1;
    }
    __syncthreads();

    if (warp == 0) {
        int j = blockIdx.x * 64 + lane;
        float d0 = 0.f, d1 = 0.f;
        #pragma unroll
        for (int r = 0; r < NWARP; r++) {
            d0 += s_red[r][lane];
            d1 += s_red[r][lane + 32];
        }
        out[N_DIM + M_DIM + j]      = fmaxf(0.f, c[j] - d0);
        out[N_DIM + M_DIM + j + 32] = fmaxf(0.f, c[j + 32] - d1);
    }
}

// ---------------------------------------------------------------------------
// kernel_launch: 3 graph nodes. Inputs (metadata order):
//   d_in[0] = c (8192), d_in[1] = A (2048*8192), d_in[2] = b (2048)
// Output: 18432 floats = concat(x[8192], lam[2048], nu[8192])
// ---------------------------------------------------------------------------
extern "C" void kernel_launch(void* const* d_in, const int* in_sizes, int n_in,
                              void* d_out, int out_size) {
    const float* c = (const float*)d_in[0];
    const float* A = (const float*)d_in[1];
    const float* b = (const float*)d_in[2];
    float* out = (float*)d_out;

    init_kernel<<<N_DIM / 256, 256>>>();
    convert_kernel<<<(M_DIM * N_DIM / 4) / 256, 256>>>(A);
    pdhg_kernel<<<NBLK, NTHR>>>(A, b, c, out);
}

// round 4
// speedup vs baseline: 1.4981x; 1.4981x over previous
#include <cuda_runtime.h>
#include <cuda_fp16.h>

#define M_DIM 2048
#define N_DIM 8192
#define N_ITERS 1000
#define TAU 1e-4f
#define SIGMA 1e-4f
#define NBLK 128
#define NTHR 1024
#define NWARP (NTHR / 32)

// Persistent state (allocation-free scratch: __device__ globals)
__device__ float g_x[N_DIM];
__device__ float g_xbar[N_DIM];
__device__ float g_y[M_DIM];
__device__ float g_lam[M_DIM];
__device__ unsigned int g_count;
__device__ unsigned int g_gen;
// fp16 copy of A, row-major, stored as half2 (32 MB)
__device__ __half2 g_Ah[(size_t)M_DIM * N_DIM / 2];

// ---------------------------------------------------------------------------
// Graph node 1: deterministic state reset on every replay
// ---------------------------------------------------------------------------
__global__ void init_kernel() {
    int i = blockIdx.x * blockDim.x + threadIdx.x;
    if (i < N_DIM) { g_x[i] = 0.f; g_xbar[i] = 0.f; }
    if (i < M_DIM) { g_y[i] = 0.f; }
    if (i == 0)    { g_count = 0u; g_gen = 0u; }
}

// ---------------------------------------------------------------------------
// Graph node 2: convert A (fp32) -> g_Ah (fp16), row-major
// ---------------------------------------------------------------------------
__global__ void __launch_bounds__(256) convert_kernel(const float* __restrict__ A) {
    size_t i = (size_t)blockIdx.x * 256 + threadIdx.x;   // over float4s
    const float4* A4 = reinterpret_cast<const float4*>(A);
    float4 v = A4[i];
    g_Ah[2 * i]     = __floats2half2_rn(v.x, v.y);
    g_Ah[2 * i + 1] = __floats2half2_rn(v.z, v.w);
}

// ---------------------------------------------------------------------------
// Software grid barrier. 128 blocks, 1/SM, co-resident by construction.
// ---------------------------------------------------------------------------
__device__ __forceinline__ void grid_sync() {
    __syncthreads();
    if (threadIdx.x == 0) {
        volatile unsigned int* vgen = &g_gen;
        unsigned int gen = *vgen;
        __threadfence();                       // release
        unsigned int t = atomicAdd(&g_count, 1u);
        if (t == NBLK - 1) {
            g_count = 0u;
            __threadfence();
            atomicAdd(&g_gen, 1u);             // release all
        } else {
            while (*vgen == gen) { }           // spin on L2
        }
        __threadfence();                       // acquire
    }
    __syncthreads();
}

// ---------------------------------------------------------------------------
// Graph node 3: whole PDHG solve, persistent, branch-free mainloops.
//   Phase Y: 2 warps per row (16 rows/block), uint4 fp16 loads, unroll 4.
//   Phase X: 32 row-groups x 32 half2-cols, coalesced 128B warp loads.
// ---------------------------------------------------------------------------
__global__ void __launch_bounds__(NTHR, 1)
pdhg_kernel(const float* __restrict__ A, const float* __restrict__ b,
            const float* __restrict__ c, float* __restrict__ out) {
    __shared__ float s_vec[N_DIM];       // 32 KB: xbar stage
    __shared__ float s_y[M_DIM];         // 8 KB: y / lam stage
    __shared__ float s_red[32][64];      // 8 KB: partial sums (aliased below)
    __shared__ float s_pair[16][2];      // phase-Y row partials

    const int tid  = threadIdx.x;
    const int warp = tid >> 5;
    const int lane = tid & 31;

    float4* s4 = reinterpret_cast<float4*>(s_vec);
    float2 (*s_red2)[32] = reinterpret_cast<float2(*)[32]>(s_red);

    // Phase-Y fixed assignment: 32 warps -> 16 rows x 2 half-rows
    const int yrow = blockIdx.x * 16 + (warp >> 1);
    const int hw   = warp & 1;                         // which half of the row
    const uint4* Arow = reinterpret_cast<const uint4*>(
        g_Ah + (size_t)yrow * (N_DIM / 2) + hw * (N_DIM / 4));

    // Phase-X fixed assignment: 32 row-groups x 32 half2 columns
    const int rg = warp;                               // row-group = warp id
    const int jc = lane;                               // half2 col within block
    const __half2* Acol = g_Ah + (size_t)blockIdx.x * 32 + jc;

    for (int it = 0; it < N_ITERS; it++) {
        // ---- Phase Y: y = min(0, y + SIGMA*(A @ xbar) - SIGMA*b) ----
        {
            const float4* x4 = reinterpret_cast<const float4*>(g_xbar);
            #pragma unroll
            for (int k = 0; k < (N_DIM / 4) / NTHR; k++)
                s4[tid + k * NTHR] = x4[tid + k * NTHR];
        }
        __syncthreads();

        {
            float acc = 0.f;
            const int sbase = hw * (N_DIM / 8);        // float4 offset of half-row
            #pragma unroll 4
            for (int k = lane; k < N_DIM / 16; k += 32) {
                uint4 a = Arow[k];
                float4 xb0 = s4[sbase + 2 * k];
                float4 xb1 = s4[sbase + 2 * k + 1];
                float2 f0 = __half22float2(*reinterpret_cast<__half2*>(&a.x));
                float2 f1 = __half22float2(*reinterpret_cast<__half2*>(&a.y));
                float2 f2 = __half22float2(*reinterpret_cast<__half2*>(&a.z));
                float2 f3 = __half22float2(*reinterpret_cast<__half2*>(&a.w));
                acc += f0.x * xb0.x + f0.y * xb0.y;
                acc += f1.x * xb0.z + f1.y * xb0.w;
                acc += f2.x * xb1.x + f2.y * xb1.y;
                acc += f3.x * xb1.z + f3.y * xb1.w;
            }
            #pragma unroll
            for (int o = 16; o > 0; o >>= 1)
                acc += __shfl_down_sync(0xffffffffu, acc, o);
            if (lane == 0) s_pair[warp >> 1][hw] = acc;
        }
        __syncthreads();

        if (tid < 16) {
            int r = blockIdx.x * 16 + tid;
            float dot = s_pair[tid][0] + s_pair[tid][1];
            g_y[r] = fminf(0.f, g_y[r] + SIGMA * dot - SIGMA * b[r]);
        }
        grid_sync();

        // ---- Phase X: x = relu(x - TAU*(A^T @ y) - TAU*c); xbar = 2x - x_old ----
        #pragma unroll
        for (int k = 0; k < M_DIM / NTHR; k++)
            s_y[tid + k * NTHR] = g_y[tid + k * NTHR];
        __syncthreads();

        {
            float2 acc = make_float2(0.f, 0.f);
            #pragma unroll 8
            for (int i = rg; i < M_DIM; i += 32) {
                float yv = s_y[i];
                float2 f = __half22float2(Acol[(size_t)i * (N_DIM / 2)]);
                acc.x += f.x * yv;
                acc.y += f.y * yv;
            }
            s_red2[rg][jc] = acc;
        }
        __syncthreads();

        if (warp == 0) {
            float2 dot = make_float2(0.f, 0.f);
            #pragma unroll
            for (int r = 0; r < 32; r++) {
                float2 p = s_red2[r][lane];
                dot.x += p.x; dot.y += p.y;
            }
            int j = blockIdx.x * 64 + 2 * lane;
            float xo0 = g_x[j], xo1 = g_x[j + 1];
            float xn0 = fmaxf(0.f, xo0 - TAU * dot.x - TAU * c[j]);
            float xn1 = fmaxf(0.f, xo1 - TAU * dot.y - TAU * c[j + 1]);
            g_x[j]        = xn0;
            g_x[j + 1]    = xn1;
            g_xbar[j]     = 2.f * xn0 - xo0;
            g_xbar[j + 1] = 2.f * xn1 - xo1;
        }
        grid_sync();
    }

    // ---- Finalize: out = [x, lam, nu] ----
    for (int i = blockIdx.x * NTHR + tid; i < N_DIM; i += NBLK * NTHR)
        out[i] = g_x[i];
    for (int i = blockIdx.x * NTHR + tid; i < M_DIM; i += NBLK * NTHR) {
        float l = fmaxf(0.f, -g_y[i]);
        g_lam[i] = l;
        out[N_DIM + i] = l;
    }
    grid_sync();

    // nu = relu(c - A^T @ lam), against the ORIGINAL fp32 A for accuracy
    #pragma unroll
    for (int k = 0; k < M_DIM / NTHR; k++)
        s_y[tid + k * NTHR] = g_lam[tid + k * NTHR];
    __syncthreads();

    {
        const int j0 = blockIdx.x * 64 + lane;
        float acc0 = 0.f, acc1 = 0.f;
        #pragma unroll 4
        for (int i = rg; i < M_DIM; i += 32) {
            float lv = s_y[i];
            acc0 += A[(size_t)i * N_DIM + j0]      * lv;
            acc1 += A[(size_t)i * N_DIM + j0 + 32] * lv;
        }
        s_red[rg][lane]      = acc0;
        s_red[rg][lane + 32] = acc1;
    }
    __syncthreads();

    if (warp == 0) {
        int j = blockIdx.x * 64 + lane;
        float d0 = 0.f, d1 = 0.f;
        #pragma unroll
        for (int r = 0; r < 32; r++) {
            d0 += s_red[r][lane];
            d1 += s_red[r][lane + 32];
        }
        out[N_DIM + M_DIM + j]      = fmaxf(0.f, c[j] - d0);
        out[N_DIM + M_DIM + j + 32] = fmaxf(0.f, c[j + 32] - d1);
    }
}

// ---------------------------------------------------------------------------
// kernel_launch: 3 graph nodes. Inputs (metadata order):
//   d_in[0] = c (8192), d_in[1] = A (2048*8192), d_in[2] = b (2048)
// Output: 18432 floats = concat(x[8192], lam[2048], nu[8192])
// ---------------------------------------------------------------------------
extern "C" void kernel_launch(void* const* d_in, const int* in_sizes, int n_in,
                              void* d_out, int out_size) {
    const float* c = (const float*)d_in[0];
    const float* A = (const float*)d_in[1];
    const float* b = (const float*)d_in[2];
    float* out = (float*)d_out;

    init_kernel<<<N_DIM / 256, 256>>>();
    convert_kernel<<<(M_DIM * N_DIM / 4) / 256, 256>>>(A);
    pdhg_kernel<<<NBLK, NTHR>>>(A, b, c, out);
}

// round 6
// speedup vs baseline: 1.7663x; 1.1790x over previous
#include <cuda_runtime.h>
#include <cuda_fp16.h>

#define M_DIM 2048
#define N_DIM 8192
#define N_ITERS 1000
#define TAU 1e-4f
#define SIGMA 1e-4f
#define NBLK 128
#define NTHR 1024

#define ROWS_PB 16          // rows owned per block
#define SROWS 12            // rows resident in SMEM
// remaining 4 rows stream from L2 (g_Ah)

// ---------------- device globals (allocation-free scratch) ----------------
__device__ float g_xbar[N_DIM];
__device__ float g_lam[M_DIM];
__device__ float g_part[NBLK * N_DIM];              // 4 MB fp32 partials
__device__ volatile unsigned g_flags[NBLK * 32];    // 1 flag / 128B line
__device__ __half2 g_Ah[(size_t)M_DIM * N_DIM / 2]; // fp16 A (32 MB)

// ---------------- smem layout (bytes) ----------------
#define OFF_PANEL 0          // 12 rows x 8192 half = 196608
#define OFF_XE    196608     // 1024 float4 (even xbar pairs) = 16384
#define OFF_XO    212992     // 1024 float4 (odd  xbar pairs) = 16384
#define OFF_RED   196608     // reuse of XE area: 16x64 fp32
#define OFF_LAM   196608     // reuse: 2048 fp32 lam stage (finale)
#define OFF_Y     229376     // 16 fp32
#define OFF_X     229440     // 64 fp32
#define OFF_C     229696     // 64 fp32
#define OFF_B     229952     // 16 fp32
#define OFF_PAIR  230016     // 16x2 fp32
#define SMEM_BYTES 230144

// ---------------------------------------------------------------------------
__global__ void init_kernel() {
    int i = blockIdx.x * blockDim.x + threadIdx.x;
    if (i < N_DIM) g_xbar[i] = 0.f;
    if (i < NBLK * 32) g_flags[i] = 0u;
}

// convert A (fp32) -> g_Ah (fp16)
__global__ void __launch_bounds__(256) convert_kernel(const float* __restrict__ A) {
    size_t i = (size_t)blockIdx.x * 256 + threadIdx.x;   // over float4s
    const float4* A4 = reinterpret_cast<const float4*>(A);
    float4 v = A4[i];
    g_Ah[2 * i]     = __floats2half2_rn(v.x, v.y);
    g_Ah[2 * i + 1] = __floats2half2_rn(v.z, v.w);
}

// ---------------------------------------------------------------------------
// Atomic-free flag barrier: 1 writer + 128 parallel pollers per block.
// Release: __threadfence before flag store. Acquire: __threadfence by thread 0
// (gpu-scope fence -> CCTL.IVALL -> SM-wide L1D invalidate) after all flags seen.
// ---------------------------------------------------------------------------
__device__ __forceinline__ void grid_barrier(unsigned target) {
    __syncthreads();
    if (threadIdx.x == 0) {
        __threadfence();
        g_flags[blockIdx.x * 32] = target;
    }
    if (threadIdx.x < NBLK) {
        while (g_flags[threadIdx.x * 32] < target) { }
    }
    __syncthreads();
    if (threadIdx.x == 0) __threadfence();
    __syncthreads();
}

__device__ __forceinline__ float dot8(uint4 a, float4 x0, float4 x1) {
    float2 f0 = __half22float2(*reinterpret_cast<__half2*>(&a.x));
    float2 f1 = __half22float2(*reinterpret_cast<__half2*>(&a.y));
    float2 f2 = __half22float2(*reinterpret_cast<__half2*>(&a.z));
    float2 f3 = __half22float2(*reinterpret_cast<__half2*>(&a.w));
    float s = f0.x * x0.x + f0.y * x0.y;
    s += f1.x * x0.z + f1.y * x0.w;
    s += f2.x * x1.x + f2.y * x1.y;
    s += f3.x * x1.z + f3.y * x1.w;
    return s;
}

// ---------------------------------------------------------------------------
__global__ void __launch_bounds__(NTHR, 1)
pdhg_kernel(const float* __restrict__ A, const float* __restrict__ b,
            const float* __restrict__ c, float* __restrict__ out) {
    extern __shared__ char sm[];
    const int tid  = threadIdx.x;
    const int warp = tid >> 5;
    const int lane = tid & 31;
    const int blk  = blockIdx.x;

    float* y_sm = (float*)(sm + OFF_Y);
    float* x_sm = (float*)(sm + OFF_X);
    float* c_sm = (float*)(sm + OFF_C);
    float* b_sm = (float*)(sm + OFF_B);
    float (*pair)[2] = (float(*)[2])(sm + OFF_PAIR);
    const uint4* GA4 = reinterpret_cast<const uint4*>(g_Ah);

    // ---- prologue: load SMEM panel (rows 0..11 of this block's slab) ----
    {
        uint4* P4 = (uint4*)(sm + OFF_PANEL);
        #pragma unroll
        for (int t = 0; t < SROWS; t++) {
            int idx = t * NTHR + tid;                 // 12 x 1024 uint4
            int r = idx >> 10, c4 = idx & 1023;
            P4[idx] = GA4[((size_t)(blk * ROWS_PB + r)) * 1024 + c4];
        }
        if (tid < ROWS_PB) { y_sm[tid] = 0.f; b_sm[tid] = b[blk * ROWS_PB + tid]; }
        if (tid < 64)      { x_sm[tid] = 0.f; c_sm[tid] = c[blk * 64 + tid]; }
    }
    __syncthreads();

    unsigned epoch = 0;
    const int yrow = warp >> 1;      // 0..15
    const int hw   = warp & 1;       // which half-row (4096 elems = 512 uint4)

    for (int it = 0; it < N_ITERS; it++) {
        // ---- stage xbar into split even/odd float4 arrays (conflict-free) ----
        {
            const float4* gx4 = (const float4*)g_xbar;
            float4* xe = (float4*)(sm + OFF_XE);
            float4* xo = (float4*)(sm + OFF_XO);
            #pragma unroll
            for (int t = 0; t < 2; t++) {
                int f = t * NTHR + tid;               // 0..2047
                float4 v = gx4[f];
                if (f & 1) xo[f >> 1] = v; else xe[f >> 1] = v;
            }
        }
        __syncthreads();

        // ---- Phase Y: y = min(0, y + SIGMA*(A@xbar) - SIGMA*b), local rows ----
        {
            const float4* xe = (const float4*)(sm + OFF_XE) + hw * 512;
            const float4* xo = (const float4*)(sm + OFF_XO) + hw * 512;
            float acc = 0.f;
            if (yrow < SROWS) {
                const uint4* Ap = (const uint4*)(sm + OFF_PANEL + yrow * 16384 + hw * 8192);
                #pragma unroll 4
                for (int k = lane; k < 512; k += 32)   // full half-row: 512 uint4
                    acc += dot8(Ap[k], xe[k], xo[k]);
            } else {
                const uint4* Ap = GA4 + ((size_t)(blk * ROWS_PB + yrow)) * 1024 + hw * 512;
                #pragma unroll 4
                for (int k = lane; k < 512; k += 32)
                    acc += dot8(Ap[k], xe[k], xo[k]);
            }
            #pragma unroll
            for (int o = 16; o > 0; o >>= 1)
                acc += __shfl_down_sync(0xffffffffu, acc, o);
            if (lane == 0) pair[yrow][hw] = acc;
        }
        __syncthreads();
        if (tid < ROWS_PB) {
            float dot = pair[tid][0] + pair[tid][1];
            y_sm[tid] = fminf(0.f, y_sm[tid] + SIGMA * dot - SIGMA * b_sm[tid]);
        }
        __syncthreads();

        // ---- Phase X partials: part[j] = sum_{i in block rows} A[i][j]*y[i] ----
        {
            float a0 = 0.f, a1 = 0.f, a2 = 0.f, a3 = 0.f;
            float a4 = 0.f, a5 = 0.f, a6 = 0.f, a7 = 0.f;
            #pragma unroll
            for (int i = 0; i < SROWS; i++) {
                float yv = y_sm[i];
                uint4 a = *(const uint4*)(sm + OFF_PANEL + i * 16384 + tid * 16);
                float2 f0 = __half22float2(*reinterpret_cast<__half2*>(&a.x));
                float2 f1 = __half22float2(*reinterpret_cast<__half2*>(&a.y));
                float2 f2 = __half22float2(*reinterpret_cast<__half2*>(&a.z));
                float2 f3 = __half22float2(*reinterpret_cast<__half2*>(&a.w));
                a0 += f0.x * yv; a1 += f0.y * yv; a2 += f1.x * yv; a3 += f1.y * yv;
                a4 += f2.x * yv; a5 += f2.y * yv; a6 += f3.x * yv; a7 += f3.y * yv;
            }
            #pragma unroll
            for (int i = SROWS; i < ROWS_PB; i++) {
                float yv = y_sm[i];
                uint4 a = GA4[((size_t)(blk * ROWS_PB + i)) * 1024 + tid];
                float2 f0 = __half22float2(*reinterpret_cast<__half2*>(&a.x));
                float2 f1 = __half22float2(*reinterpret_cast<__half2*>(&a.y));
                float2 f2 = __half22float2(*reinterpret_cast<__half2*>(&a.z));
                float2 f3 = __half22float2(*reinterpret_cast<__half2*>(&a.w));
                a0 += f0.x * yv; a1 += f0.y * yv; a2 += f1.x * yv; a3 += f1.y * yv;
                a4 += f2.x * yv; a5 += f2.y * yv; a6 += f3.x * yv; a7 += f3.y * yv;
            }
            float4* P4 = (float4*)(g_part + (size_t)blk * N_DIM + tid * 8);
            P4[0] = make_float4(a0, a1, a2, a3);
            P4[1] = make_float4(a4, a5, a6, a7);
        }
        grid_barrier(++epoch);

        // ---- Reduce 128 partials for this block's 64 columns; update x, xbar ----
        {
            float* sred = (float*)(sm + OFF_RED);
            int g  = tid >> 6;
            int jc = tid & 63;
            float r = 0.f;
            #pragma unroll
            for (int p = g; p < NBLK; p += 16)
                r += g_part[(size_t)p * N_DIM + blk * 64 + jc];
            sred[g * 64 + jc] = r;
            __syncthreads();
            if (tid < 64) {
                float dot = 0.f;
                #pragma unroll
                for (int gg = 0; gg < 16; gg++) dot += sred[gg * 64 + tid];
                float xo = x_sm[tid];
                float xn = fmaxf(0.f, xo - TAU * dot - TAU * c_sm[tid]);
                x_sm[tid] = xn;
                g_xbar[blk * 64 + tid] = 2.f * xn - xo;
            }
        }
        grid_barrier(++epoch);
    }

    // ---- Finalize: out = [x, lam, nu] ----
    if (tid < 64) out[blk * 64 + tid] = x_sm[tid];
    if (tid < ROWS_PB) {
        float l = fmaxf(0.f, -y_sm[tid]);
        g_lam[blk * ROWS_PB + tid] = l;
        out[N_DIM + blk * ROWS_PB + tid] = l;
    }
    grid_barrier(++epoch);

    // nu = relu(c - A^T @ lam), against ORIGINAL fp32 A (one pass, accuracy)
    {
        float* s_lam = (float*)(sm + OFF_LAM);
        #pragma unroll
        for (int t = 0; t < 2; t++) {
            int i = t * NTHR + tid;
            if (i < M_DIM) s_lam[i] = g_lam[i];
        }
        __syncthreads();

        float* sred = (float*)(sm + OFF_XO);
        int g  = tid >> 6;
        int jc = tid & 63;
        float acc = 0.f;
        for (int i = g; i < M_DIM; i += 16)
            acc += A[(size_t)i * N_DIM + blk * 64 + jc] * s_lam[i];
        sred[g * 64 + jc] = acc;
        __syncthreads();
        if (tid < 64) {
            float dot = 0.f;
            #pragma unroll
            for (int gg = 0; gg < 16; gg++) dot += sred[gg * 64 + tid];
            out[N_DIM + M_DIM + blk * 64 + tid] = fmaxf(0.f, c_sm[tid] - dot);
        }
    }
}

// ---------------------------------------------------------------------------
// kernel_launch: 3 graph nodes. Inputs (metadata order):
//   d_in[0] = c (8192), d_in[1] = A (2048*8192), d_in[2] = b (2048)
// Output: 18432 floats = concat(x[8192], lam[2048], nu[8192])
// ---------------------------------------------------------------------------
extern "C" void kernel_launch(void* const* d_in, const int* in_sizes, int n_in,
                              void* d_out, int out_size) {
    const float* c = (const float*)d_in[0];
    const float* A = (const float*)d_in[1];
    const float* b = (const float*)d_in[2];
    float* out = (float*)d_out;

    cudaFuncSetAttribute(pdhg_kernel,
                         cudaFuncAttributeMaxDynamicSharedMemorySize, SMEM_BYTES);

    init_kernel<<<32, 256>>>();
    convert_kernel<<<(M_DIM * N_DIM / 4) / 256, 256>>>(A);
    pdhg_kernel<<<NBLK, NTHR, SMEM_BYTES>>>(A, b, c, out);
}

// round 7
// speedup vs baseline: 1.9460x; 1.1018x over previous
#include <cuda_runtime.h>
#include <cuda_fp16.h>

#define M_DIM 2048
#define N_DIM 8192
#define N_ITERS 1000
#define TAU 1e-4f
#define SIGMA 1e-4f
#define NBLK 128
#define NTHR 1024

#define ROWS_PB 16          // rows owned per block
#define SROWS 13            // rows resident in SMEM; 3 streamed from L2

// ---------------- device globals (allocation-free scratch) ----------------
__device__ float g_xbar[N_DIM];
__device__ float g_lam[M_DIM];
__device__ float g_part[NBLK * N_DIM];              // 4 MB fp32 partials
__device__ volatile unsigned g_flags[NBLK * 32];    // 1 flag / 128B line
__device__ __half2 g_Ah[(size_t)M_DIM * N_DIM / 2]; // fp16 A (32 MB)

// ---------------- smem layout (bytes) ----------------
#define OFF_PANEL 0                       // 13 rows x 8192 half = 212992
#define OFF_RED   212992                  // 16x64 fp32 = 4096 (covers both uses)
#define OFF_Y     (OFF_RED + 4096)        // 16 fp32
#define OFF_X     (OFF_Y + 64)            // 64 fp32
#define OFF_C     (OFF_X + 256)           // 64 fp32
#define OFF_B     (OFF_C + 256)           // 16 fp32
#define SMEM_BYTES (OFF_B + 64)           // = 217664 + 64 = 217728... computed below
// finale reuse of panel area:
#define OFF_LAM   0                       // 2048 fp32 = 8192
#define OFF_SRED2 8192                    // 16x64 fp32 = 4096

// ---------------------------------------------------------------------------
__global__ void init_kernel() {
    int i = blockIdx.x * blockDim.x + threadIdx.x;
    if (i < N_DIM) g_xbar[i] = 0.f;
    if (i < NBLK * 32) g_flags[i] = 0u;
}

// convert A (fp32) -> g_Ah (fp16)
__global__ void __launch_bounds__(256) convert_kernel(const float* __restrict__ A) {
    size_t i = (size_t)blockIdx.x * 256 + threadIdx.x;   // over float4s
    const float4* A4 = reinterpret_cast<const float4*>(A);
    float4 v = A4[i];
    g_Ah[2 * i]     = __floats2half2_rn(v.x, v.y);
    g_Ah[2 * i + 1] = __floats2half2_rn(v.z, v.w);
}

// ---------------------------------------------------------------------------
// Atomic-free flag barrier: 1 writer + 128 parallel pollers per block.
// ---------------------------------------------------------------------------
__device__ __forceinline__ void grid_barrier(unsigned target) {
    __syncthreads();
    if (threadIdx.x == 0) {
        __threadfence();                       // release
        g_flags[blockIdx.x * 32] = target;
    }
    if (threadIdx.x < NBLK) {
        while (g_flags[threadIdx.x * 32] < target) { }
    }
    __syncthreads();
    if (threadIdx.x == 0) __threadfence();     // acquire (L1D invalidate)
    __syncthreads();
}

__device__ __forceinline__ float dot8(uint4 a, float4 x0, float4 x1) {
    float2 f0 = __half22float2(*reinterpret_cast<__half2*>(&a.x));
    float2 f1 = __half22float2(*reinterpret_cast<__half2*>(&a.y));
    float2 f2 = __half22float2(*reinterpret_cast<__half2*>(&a.z));
    float2 f3 = __half22float2(*reinterpret_cast<__half2*>(&a.w));
    float s = f0.x * x0.x + f0.y * x0.y;
    s += f1.x * x0.z + f1.y * x0.w;
    s += f2.x * x1.x + f2.y * x1.y;
    s += f3.x * x1.z + f3.y * x1.w;
    return s;
}

// ---------------------------------------------------------------------------
__global__ void __launch_bounds__(NTHR, 1)
pdhg_kernel(const float* __restrict__ A, const float* __restrict__ b,
            const float* __restrict__ c, float* __restrict__ out) {
    extern __shared__ char sm[];
    const int tid  = threadIdx.x;
    const int warp = tid >> 5;
    const int lane = tid & 31;
    const int blk  = blockIdx.x;

    float* s_red = (float*)(sm + OFF_RED);
    float* y_sm  = (float*)(sm + OFF_Y);
    float* x_sm  = (float*)(sm + OFF_X);
    float* c_sm  = (float*)(sm + OFF_C);
    float* b_sm  = (float*)(sm + OFF_B);
    const uint4* GA4 = reinterpret_cast<const uint4*>(g_Ah);
    const uint4* P4  = (const uint4*)(sm + OFF_PANEL);

    // ---- prologue: load SMEM panel (rows 0..12 of this block's slab) ----
    {
        uint4* W4 = (uint4*)(sm + OFF_PANEL);
        #pragma unroll
        for (int t = 0; t < SROWS; t++) {
            int idx = t * NTHR + tid;                 // 13 x 1024 uint4
            int r = idx >> 10, c4 = idx & 1023;
            W4[idx] = GA4[((size_t)(blk * ROWS_PB + r)) * 1024 + c4];
        }
        if (tid < ROWS_PB) { y_sm[tid] = 0.f; b_sm[tid] = b[blk * ROWS_PB + tid]; }
        if (tid < 64)      { x_sm[tid] = 0.f; c_sm[tid] = c[blk * 64 + tid]; }
    }
    __syncthreads();

    unsigned epoch = 0;
    const int u4 = warp * 32 + lane;                  // lane's uint4 column chunk

    for (int it = 0; it < N_ITERS; it++) {
        // ---- Phase Y: register-blocked A@xbar over this block's 16 rows ----
        {
            const float4* gx4 = (const float4*)g_xbar;
            float4 x0 = gx4[2 * u4];                  // lane's 8 xbar values (LDG once)
            float4 x1 = gx4[2 * u4 + 1];

            float acc[ROWS_PB];
            #pragma unroll
            for (int i = 0; i < SROWS; i++)
                acc[i] = dot8(P4[i * 1024 + u4], x0, x1);
            #pragma unroll
            for (int i = SROWS; i < ROWS_PB; i++)
                acc[i] = dot8(GA4[((size_t)(blk * ROWS_PB + i)) * 1024 + u4], x0, x1);

            #pragma unroll
            for (int r = 0; r < ROWS_PB; r++) {
                float v = acc[r];
                #pragma unroll
                for (int o = 16; o > 0; o >>= 1)
                    v += __shfl_down_sync(0xffffffffu, v, o);
                if (lane == 0) s_red[r * 32 + warp] = v;
            }
        }
        __syncthreads();
        if (warp < ROWS_PB) {
            float v = s_red[warp * 32 + lane];
            #pragma unroll
            for (int o = 16; o > 0; o >>= 1)
                v += __shfl_down_sync(0xffffffffu, v, o);
            if (lane == 0)
                y_sm[warp] = fminf(0.f, y_sm[warp] + SIGMA * v - SIGMA * b_sm[warp]);
        }
        __syncthreads();

        // ---- Phase X partials: part[j] = sum_{i in block rows} A[i][j]*y[i] ----
        {
            float a0 = 0.f, a1 = 0.f, a2 = 0.f, a3 = 0.f;
            float a4 = 0.f, a5 = 0.f, a6 = 0.f, a7 = 0.f;
            #pragma unroll
            for (int i = 0; i < SROWS; i++) {
                float yv = y_sm[i];
                uint4 a = P4[i * 1024 + tid];
                float2 f0 = __half22float2(*reinterpret_cast<__half2*>(&a.x));
                float2 f1 = __half22float2(*reinterpret_cast<__half2*>(&a.y));
                float2 f2 = __half22float2(*reinterpret_cast<__half2*>(&a.z));
                float2 f3 = __half22float2(*reinterpret_cast<__half2*>(&a.w));
                a0 += f0.x * yv; a1 += f0.y * yv; a2 += f1.x * yv; a3 += f1.y * yv;
                a4 += f2.x * yv; a5 += f2.y * yv; a6 += f3.x * yv; a7 += f3.y * yv;
            }
            #pragma unroll
            for (int i = SROWS; i < ROWS_PB; i++) {
                float yv = y_sm[i];
                uint4 a = GA4[((size_t)(blk * ROWS_PB + i)) * 1024 + tid];
                float2 f0 = __half22float2(*reinterpret_cast<__half2*>(&a.x));
                float2 f1 = __half22float2(*reinterpret_cast<__half2*>(&a.y));
                float2 f2 = __half22float2(*reinterpret_cast<__half2*>(&a.z));
                float2 f3 = __half22float2(*reinterpret_cast<__half2*>(&a.w));
                a0 += f0.x * yv; a1 += f0.y * yv; a2 += f1.x * yv; a3 += f1.y * yv;
                a4 += f2.x * yv; a5 += f2.y * yv; a6 += f3.x * yv; a7 += f3.y * yv;
            }
            float4* O4 = (float4*)(g_part + (size_t)blk * N_DIM + tid * 8);
            O4[0] = make_float4(a0, a1, a2, a3);
            O4[1] = make_float4(a4, a5, a6, a7);
        }
        grid_barrier(++epoch);

        // ---- Reduce 128 partials for this block's 64 columns; update x, xbar ----
        {
            int g  = tid >> 6;
            int jc = tid & 63;
            float r = 0.f;
            #pragma unroll
            for (int p = g; p < NBLK; p += 16)
                r += g_part[(size_t)p * N_DIM + blk * 64 + jc];
            s_red[g * 64 + jc] = r;
            __syncthreads();
            if (tid < 64) {
                float dot = 0.f;
                #pragma unroll
                for (int gg = 0; gg < 16; gg++) dot += s_red[gg * 64 + tid];
                float xo = x_sm[tid];
                float xn = fmaxf(0.f, xo - TAU * dot - TAU * c_sm[tid]);
                x_sm[tid] = xn;
                g_xbar[blk * 64 + tid] = 2.f * xn - xo;
            }
        }
        grid_barrier(++epoch);
    }

    // ---- Finalize: out = [x, lam, nu] ----
    if (tid < 64) out[blk * 64 + tid] = x_sm[tid];
    if (tid < ROWS_PB) {
        float l = fmaxf(0.f, -y_sm[tid]);
        g_lam[blk * ROWS_PB + tid] = l;
        out[N_DIM + blk * ROWS_PB + tid] = l;
    }
    grid_barrier(++epoch);

    // nu = relu(c - A^T @ lam), against ORIGINAL fp32 A (one pass, accuracy)
    {
        float* s_lam = (float*)(sm + OFF_LAM);
        #pragma unroll
        for (int t = 0; t < 2; t++) {
            int i = t * NTHR + tid;
            if (i < M_DIM) s_lam[i] = g_lam[i];
        }
        __syncthreads();

        float* sred2 = (float*)(sm + OFF_SRED2);
        int g  = tid >> 6;
        int jc = tid & 63;
        float acc = 0.f;
        for (int i = g; i < M_DIM; i += 16)
            acc += A[(size_t)i * N_DIM + blk * 64 + jc] * s_lam[i];
        sred2[g * 64 + jc] = acc;
        __syncthreads();
        if (tid < 64) {
            float dot = 0.f;
            #pragma unroll
            for (int gg = 0; gg < 16; gg++) dot += sred2[gg * 64 + tid];
            out[N_DIM + M_DIM + blk * 64 + tid] = fmaxf(0.f, c_sm[tid] - dot);
        }
    }
}

// ---------------------------------------------------------------------------
// kernel_launch: 3 graph nodes. Inputs (metadata order):
//   d_in[0] = c (8192), d_in[1] = A (2048*8192), d_in[2] = b (2048)
// Output: 18432 floats = concat(x[8192], lam[2048], nu[8192])
// ---------------------------------------------------------------------------
extern "C" void kernel_launch(void* const* d_in, const int* in_sizes, int n_in,
                              void* d_out, int out_size) {
    const float* c = (const float*)d_in[0];
    const float* A = (const float*)d_in[1];
    const float* b = (const float*)d_in[2];
    float* out = (float*)d_out;

    cudaFuncSetAttribute(pdhg_kernel,
                         cudaFuncAttributeMaxDynamicSharedMemorySize, SMEM_BYTES);

    init_kernel<<<32, 256>>>();
    convert_kernel<<<(M_DIM * N_DIM / 4) / 256, 256>>>(A);
    pdhg_kernel<<<NBLK, NTHR, SMEM_BYTES>>>(A, b, c, out);
}

// round 8
// speedup vs baseline: 2.0253x; 1.0407x over previous
#include <cuda_runtime.h>
#include <cuda_fp16.h>

#define M_DIM 2048
#define N_DIM 8192
#define N_ITERS 1000
#define TAU 1e-4f
#define SIGMA 1e-4f
#define NBLK 148
#define NTHR 1024

#define PROWS 13            // panel rows resident in SMEM
#define RPAD 14             // rows processed per block (13 panel + 1 register)

// ---------------- device globals (allocation-free scratch) ----------------
__device__ float g_xbar[N_DIM];
__device__ float g_lam[M_DIM];
__device__ float g_part[NBLK * N_DIM];              // ~4.85 MB fp32 partials
__device__ volatile unsigned g_flags[NBLK * 32];    // 1 flag / 128B line
__device__ __half2 g_Ah[(size_t)M_DIM * N_DIM / 2]; // fp16 A (32 MB)

// ---------------- smem layout (bytes) ----------------
#define OFF_PANEL 0                        // 13 rows x 8192 half = 212992
#define OFF_RED   (PROWS * N_DIM * 2)      // 16x64 fp32 = 4096
#define OFF_Y     (OFF_RED + 4096)         // 16 fp32
#define OFF_X     (OFF_Y + 64)             // 64 fp32
#define OFF_C     (OFF_X + 256)            // 64 fp32
#define OFF_B     (OFF_C + 256)            // 16 fp32
#define SMEM_BYTES (OFF_B + 64)            // 217728 < 227 KB
#define OFF_LAM   0                        // finale reuse of panel: 2048 fp32

// ---------------------------------------------------------------------------
__global__ void init_kernel() {
    int i = blockIdx.x * blockDim.x + threadIdx.x;
    if (i < N_DIM) g_xbar[i] = 0.f;
    if (i < NBLK * 32) g_flags[i] = 0u;
}

__global__ void __launch_bounds__(256) convert_kernel(const float* __restrict__ A) {
    size_t i = (size_t)blockIdx.x * 256 + threadIdx.x;   // over float4s
    const float4* A4 = reinterpret_cast<const float4*>(A);
    float4 v = A4[i];
    g_Ah[2 * i]     = __floats2half2_rn(v.x, v.y);
    g_Ah[2 * i + 1] = __floats2half2_rn(v.z, v.w);
}

// ---------------------------------------------------------------------------
// Atomic-free flag barrier (proven in R6/R7): release fence + flag store;
// 148 parallel pollers; acquire fence (CCTL.IVALL) before proceeding.
// ---------------------------------------------------------------------------
__device__ __forceinline__ void grid_barrier(unsigned target) {
    __syncthreads();
    if (threadIdx.x == 0) {
        __threadfence();
        g_flags[blockIdx.x * 32] = target;
    }
    if (threadIdx.x < NBLK) {
        while (g_flags[threadIdx.x * 32] < target) { }
    }
    __syncthreads();
    if (threadIdx.x == 0) __threadfence();
    __syncthreads();
}

// convert 8 fp16 (uint4) -> 8 fp32
__device__ __forceinline__ void cvt8(uint4 a, float* f) {
    float2 t;
    t = __half22float2(*reinterpret_cast<__half2*>(&a.x)); f[0] = t.x; f[1] = t.y;
    t = __half22float2(*reinterpret_cast<__half2*>(&a.y)); f[2] = t.x; f[3] = t.y;
    t = __half22float2(*reinterpret_cast<__half2*>(&a.z)); f[4] = t.x; f[5] = t.y;
    t = __half22float2(*reinterpret_cast<__half2*>(&a.w)); f[6] = t.x; f[7] = t.y;
}

__device__ __forceinline__ unsigned long long pack2(float lo, float hi) {
    unsigned long long r;
    asm("mov.b64 %0, {%1, %2};" : "=l"(r) : "f"(lo), "f"(hi));
    return r;
}
__device__ __forceinline__ void unpack2(unsigned long long v, float& lo, float& hi) {
    asm("mov.b64 {%0, %1}, %2;" : "=f"(lo), "=f"(hi) : "l"(v));
}
__device__ __forceinline__ void ffma2(unsigned long long& acc,
                                      unsigned long long a, unsigned long long b) {
    asm("fma.rn.f32x2 %0, %1, %2, %0;" : "+l"(acc) : "l"(a), "l"(b));
}

// ---------------------------------------------------------------------------
__global__ void __launch_bounds__(NTHR, 1)
pdhg_kernel(const float* __restrict__ A, const float* __restrict__ b,
            const float* __restrict__ c, float* __restrict__ out) {
    extern __shared__ char sm[];
    const int tid  = threadIdx.x;
    const int warp = tid >> 5;
    const int lane = tid & 31;
    const int blk  = blockIdx.x;

    // balanced ownership
    const int r0 = (blk * M_DIM) / NBLK;
    const int nr = ((blk + 1) * M_DIM) / NBLK - r0;   // 13 or 14
    const int c0 = (blk * N_DIM) / NBLK;
    const int nc = ((blk + 1) * N_DIM) / NBLK - c0;   // 55 or 56

    float* s_red = (float*)(sm + OFF_RED);
    float* y_sm  = (float*)(sm + OFF_Y);
    float* x_sm  = (float*)(sm + OFF_X);
    float* c_sm  = (float*)(sm + OFF_C);
    float* b_sm  = (float*)(sm + OFF_B);
    const uint4* GA4 = reinterpret_cast<const uint4*>(g_Ah);
    const uint4* P4  = (const uint4*)(sm + OFF_PANEL);

    // ---- prologue: 13 panel rows -> SMEM; 14th row -> registers forever ----
    {
        uint4* W4 = (uint4*)(sm + OFF_PANEL);
        #pragma unroll
        for (int r = 0; r < PROWS; r++)
            W4[r * 1024 + tid] = GA4[((size_t)(r0 + r)) * 1024 + tid];
        if (tid < 16) y_sm[tid] = 0.f;                 // incl. padded row
        if (tid < nr) b_sm[tid] = b[r0 + tid];
        if (tid < nc) { x_sm[tid] = 0.f; c_sm[tid] = c[blk == 0 ? tid : c0 + tid]; }
    }
    const uint4 a_stream = GA4[((size_t)(r0 + PROWS)) * 1024 + tid];  // row 13 (or neighbor, y=0)
    __syncthreads();

    unsigned epoch = 0;

    for (int it = 0; it < N_ITERS; it++) {
        // ================= Phase Y: y = min(0, y + s*(A@xbar) - s*b) =======
        float v[16];
        {
            const float4* gx4 = (const float4*)g_xbar;
            float4 xa = gx4[2 * tid];
            float4 xb = gx4[2 * tid + 1];
            unsigned long long xv2[8];
            xv2[0] = pack2(xa.x, xa.x); xv2[1] = pack2(xa.y, xa.y);
            xv2[2] = pack2(xa.z, xa.z); xv2[3] = pack2(xa.w, xa.w);
            xv2[4] = pack2(xb.x, xb.x); xv2[5] = pack2(xb.y, xb.y);
            xv2[6] = pack2(xb.z, xb.z); xv2[7] = pack2(xb.w, xb.w);

            unsigned long long acc2[7];
            #pragma unroll
            for (int p = 0; p < 7; p++) {
                uint4 ua = P4[(2 * p) * 1024 + tid];
                uint4 ub = (2 * p + 1 < PROWS) ? P4[(2 * p + 1) * 1024 + tid]
                                               : a_stream;
                float fa[8], fb[8];
                cvt8(ua, fa); cvt8(ub, fb);
                unsigned long long acc = 0ull;
                #pragma unroll
                for (int k = 0; k < 8; k++)
                    ffma2(acc, pack2(fa[k], fb[k]), xv2[k]);
                acc2[p] = acc;
            }
            #pragma unroll
            for (int p = 0; p < 7; p++) unpack2(acc2[p], v[2 * p], v[2 * p + 1]);
            v[14] = 0.f; v[15] = 0.f;
        }
        // butterfly multi-row warp reduction: 16 rows -> 1 row per even lane
        {
            #pragma unroll
            for (int k = 0; k < 8; k++) {
                float s = (lane & 16) ? v[k] : v[k + 8];
                float r = __shfl_xor_sync(0xffffffffu, s, 16);
                v[k] = ((lane & 16) ? v[k + 8] : v[k]) + r;
            }
            #pragma unroll
            for (int k = 0; k < 4; k++) {
                float s = (lane & 8) ? v[k] : v[k + 4];
                float r = __shfl_xor_sync(0xffffffffu, s, 8);
                v[k] = ((lane & 8) ? v[k + 4] : v[k]) + r;
            }
            #pragma unroll
            for (int k = 0; k < 2; k++) {
                float s = (lane & 4) ? v[k] : v[k + 2];
                float r = __shfl_xor_sync(0xffffffffu, s, 4);
                v[k] = ((lane & 4) ? v[k + 2] : v[k]) + r;
            }
            {
                float s = (lane & 2) ? v[0] : v[1];
                float r = __shfl_xor_sync(0xffffffffu, s, 2);
                v[0] = ((lane & 2) ? v[1] : v[0]) + r;
            }
            v[0] += __shfl_xor_sync(0xffffffffu, v[0], 1);
            int row = (((lane >> 4) & 1) << 3) | (((lane >> 3) & 1) << 2) |
                      (((lane >> 2) & 1) << 1) | ((lane >> 1) & 1);
            if ((lane & 1) == 0) s_red[row * 32 + warp] = v[0];
        }
        __syncthreads();
        if (warp < 16) {
            float t = s_red[warp * 32 + lane];
            #pragma unroll
            for (int o = 16; o > 0; o >>= 1)
                t += __shfl_down_sync(0xffffffffu, t, o);
            if (lane == 0 && warp < nr)
                y_sm[warp] = fminf(0.f, y_sm[warp] + SIGMA * t - SIGMA * b_sm[warp]);
        }
        __syncthreads();

        // ============ Phase X partials: part[j] = sum_i A[i][j]*y[i] =======
        {
            unsigned long long xacc[4] = {0ull, 0ull, 0ull, 0ull};
            #pragma unroll
            for (int i = 0; i < RPAD; i++) {
                float yv = y_sm[i];                       // 0 for padded row
                unsigned long long yv2 = pack2(yv, yv);
                uint4 a = (i < PROWS) ? P4[i * 1024 + tid] : a_stream;
                float f[8];
                cvt8(a, f);
                ffma2(xacc[0], pack2(f[0], f[1]), yv2);
                ffma2(xacc[1], pack2(f[2], f[3]), yv2);
                ffma2(xacc[2], pack2(f[4], f[5]), yv2);
                ffma2(xacc[3], pack2(f[6], f[7]), yv2);
            }
            float o0, o1, o2, o3, o4, o5, o6, o7;
            unpack2(xacc[0], o0, o1); unpack2(xacc[1], o2, o3);
            unpack2(xacc[2], o4, o5); unpack2(xacc[3], o6, o7);
            float4* O4 = (float4*)(g_part + (size_t)blk * N_DIM + tid * 8);
            O4[0] = make_float4(o0, o1, o2, o3);
            O4[1] = make_float4(o4, o5, o6, o7);
        }
        grid_barrier(++epoch);

        // ===== Reduce 148 partials for this block's nc columns =============
        {
            int g  = tid >> 6;
            int jc = tid & 63;
            if (jc < nc) {
                float r = 0.f;
                for (int p = g; p < NBLK; p += 16)
                    r += g_part[(size_t)p * N_DIM + c0 + jc];
                s_red[g * 64 + jc] = r;
            }
            __syncthreads();
            if (tid < nc) {
                float dot = 0.f;
                #pragma unroll
                for (int gg = 0; gg < 16; gg++) dot += s_red[gg * 64 + tid];
                float xo = x_sm[tid];
                float xn = fmaxf(0.f, xo - TAU * dot - TAU * c_sm[tid]);
                x_sm[tid] = xn;
                g_xbar[c0 + tid] = 2.f * xn - xo;
            }
        }
        grid_barrier(++epoch);
    }

    // ---- Finalize: out = [x, lam, nu] ----
    if (tid < nc) out[c0 + tid] = x_sm[tid];
    if (tid < nr) {
        float l = fmaxf(0.f, -y_sm[tid]);
        g_lam[r0 + tid] = l;
        out[N_DIM + r0 + tid] = l;
    }
    grid_barrier(++epoch);

    // nu = relu(c - A^T @ lam), against ORIGINAL fp32 A (one pass, accuracy)
    {
        float* s_lam = (float*)(sm + OFF_LAM);
        #pragma unroll
        for (int t = 0; t < 2; t++) {
            int i = t * NTHR + tid;
            if (i < M_DIM) s_lam[i] = g_lam[i];
        }
        __syncthreads();

        int g  = tid >> 6;
        int jc = tid & 63;
        if (jc < nc) {
            float acc = 0.f;
            for (int i = g; i < M_DIM; i += 16)
                acc += A[(size_t)i * N_DIM + c0 + jc] * s_lam[i];
            s_red[g * 64 + jc] = acc;
        }
        __syncthreads();
        if (tid < nc) {
            float dot = 0.f;
            #pragma unroll
            for (int gg = 0; gg < 16; gg++) dot += s_red[gg * 64 + tid];
            out[N_DIM + M_DIM + c0 + tid] = fmaxf(0.f, c_sm[tid] - dot);
        }
    }
}

// ---------------------------------------------------------------------------
// kernel_launch: 3 graph nodes. Inputs (metadata order):
//   d_in[0] = c (8192), d_in[1] = A (2048*8192), d_in[2] = b (2048)
// Output: 18432 floats = concat(x[8192], lam[2048], nu[8192])
// ---------------------------------------------------------------------------
extern "C" void kernel_launch(void* const* d_in, const int* in_sizes, int n_in,
                              void* d_out, int out_size) {
    const float* c = (const float*)d_in[0];
    const float* A = (const float*)d_in[1];
    const float* b = (const float*)d_in[2];
    float* out = (float*)d_out;

    cudaFuncSetAttribute(pdhg_kernel,
                         cudaFuncAttributeMaxDynamicSharedMemorySize, SMEM_BYTES);

    init_kernel<<<32, 256>>>();
    convert_kernel<<<(M_DIM * N_DIM / 4) / 256, 256>>>(A);
    pdhg_kernel<<<NBLK, NTHR, SMEM_BYTES>>>(A, b, c, out);
}